// round 5
// baseline (speedup 1.0000x reference)
#include <cuda_runtime.h>
#include <cstdint>

#define T_LEN 512
#define B_SZ  2048
#define HID   23
#define G3    69       // 3*H
#define FIN   32
#define D2    46       // 2*H
#define OUTD  8
#define M_ROWS (T_LEN * B_SZ)   // 1,048,576

// ---------------- scratch (device globals; no allocation) ----------------
__device__ float g_xnorm[(size_t)M_ROWS * FIN];      // [T][B][32]   134 MB
__device__ float g_xg[(size_t)2 * M_ROWS * G3];      // [dir][T*B][69] 579 MB
__device__ float g_seqA[(size_t)M_ROWS * D2];        // [T][B][46]   193 MB
__device__ float g_seqB[(size_t)M_ROWS * D2];        // [T][B][46]   193 MB

__device__ __forceinline__ float sigf(float x) {
    return 1.0f / (1.0f + __expf(-x));
}
__device__ __forceinline__ float tanh_fast(float x) {
    float a = __expf(-2.0f * fabsf(x));
    float t = (1.0f - a) / (1.0f + a);
    return copysignf(t, x);
}

// ---------------- 1) normalize + transpose [B,T,F] -> [T,B,F] ----------------
__global__ void norm_kernel(const float* __restrict__ x,
                            const float* __restrict__ fmean,
                            const float* __restrict__ fstd) {
    size_t idx = (size_t)blockIdx.x * blockDim.x + threadIdx.x;
    size_t total = (size_t)M_ROWS * FIN;
    if (idx >= total) return;
    int i = (int)(idx % FIN);
    size_t tb = idx / FIN;
    int b = (int)(tb % B_SZ);
    int t = (int)(tb / B_SZ);
    float s = fstd[i];
    s = (s == 0.0f) ? 1.0f : s;
    float v;
    if (s == 1.0f) {
        v = 0.0f;
    } else {
        v = (x[((size_t)b * T_LEN + t) * FIN + i] - fmean[i]) / s;
    }
    g_xnorm[idx] = v;
}

// ---------------- 2) input-gate GEMM: xg[d][row][g] = in[row] . Wih[d][g] + b ----------------
// tile: 128 rows x 72 cols (69 real). block = 288 threads; each thread 8 rows x 4 cols.
template <int K>
__global__ __launch_bounds__(288)
void xg_kernel(int insel, const float* __restrict__ w_ih, const float* __restrict__ b_ih) {
    const float* in = (K == FIN) ? g_xnorm : ((insel == 1) ? g_seqA : g_seqB);
    const int d = blockIdx.y;
    const float* W = w_ih + (size_t)d * G3 * K;

    __shared__ float xs[128][K + 1];
    __shared__ float ws[72][K + 1];
    __shared__ float bs[72];

    const int tid = threadIdx.x;
    const size_t rowbase = (size_t)blockIdx.x * 128;

    for (int idx = tid; idx < 128 * K; idx += 288) {
        int r = idx / K, k = idx % K;
        xs[r][k] = in[(rowbase + r) * K + k];
    }
    for (int idx = tid; idx < 72 * K; idx += 288) {
        int g = idx / K, k = idx % K;
        ws[g][k] = (g < G3) ? W[g * K + k] : 0.0f;
    }
    if (tid < 72) bs[tid] = (tid < G3) ? b_ih[d * G3 + tid] : 0.0f;
    __syncthreads();

    const int cg = tid % 18;   // 18 col-groups of 4 -> 72
    const int rg = tid / 18;   // 16 row-groups of 8 -> 128
    const int g0 = cg * 4;
    const int r0 = rg * 8;

    float acc[8][4];
#pragma unroll
    for (int i = 0; i < 8; i++)
#pragma unroll
        for (int j = 0; j < 4; j++) acc[i][j] = 0.0f;

#pragma unroll
    for (int k = 0; k < K; k++) {
        float w0 = ws[g0 + 0][k];
        float w1 = ws[g0 + 1][k];
        float w2 = ws[g0 + 2][k];
        float w3 = ws[g0 + 3][k];
#pragma unroll
        for (int i = 0; i < 8; i++) {
            float xv = xs[r0 + i][k];
            acc[i][0] += xv * w0;
            acc[i][1] += xv * w1;
            acc[i][2] += xv * w2;
            acc[i][3] += xv * w3;
        }
    }

    float b0 = bs[g0 + 0], b1 = bs[g0 + 1], b2 = bs[g0 + 2], b3 = bs[g0 + 3];
    float* xg = g_xg + (size_t)d * M_ROWS * G3;
#pragma unroll
    for (int i = 0; i < 8; i++) {
        size_t rbase = (rowbase + r0 + i) * (size_t)G3;
        if (g0 + 0 < G3) xg[rbase + g0 + 0] = acc[i][0] + b0;
        if (g0 + 1 < G3) xg[rbase + g0 + 1] = acc[i][1] + b1;
        if (g0 + 2 < G3) xg[rbase + g0 + 2] = acc[i][2] + b2;
        if (g0 + 3 < G3) xg[rbase + g0 + 3] = acc[i][3] + b3;
    }
}

// ---------------- 3) GRU recurrence: one warp per (batch row, dir) ----------------
__global__ __launch_bounds__(128)
void gru_kernel(const float* __restrict__ w_hh, const float* __restrict__ b_hh, int outsel) {
    const int d = blockIdx.y;
    const int warp = threadIdx.x >> 5;
    const int lane = threadIdx.x & 31;
    const int b = blockIdx.x * 4 + warp;
    float* seq_out = (outsel == 1) ? g_seqA : g_seqB;

    __shared__ float hs[4][24];

    const float* W = w_hh + (size_t)d * G3 * HID;
    const float* bh = b_hh + d * G3;

    float wr[HID], wz[HID], wn[HID];
    float br = 0.0f, bz = 0.0f, bn = 0.0f;
    const int j = lane;
    const bool active = (j < HID);
    if (active) {
#pragma unroll
        for (int k = 0; k < HID; k++) {
            wr[k] = W[(j) * HID + k];
            wz[k] = W[(j + HID) * HID + k];
            wn[k] = W[(j + 2 * HID) * HID + k];
        }
        br = bh[j];
        bz = bh[j + HID];
        bn = bh[j + 2 * HID];
        hs[warp][j] = 0.0f;
    }
    float h = 0.0f;
    __syncwarp();

    const float* xgd = g_xg + (size_t)d * M_ROWS * G3;
    const int t0 = (d == 0) ? 0 : (T_LEN - 1);
    const int dt = (d == 0) ? 1 : -1;

    float xr_n = 0.0f, xz_n = 0.0f, xn_n = 0.0f;
    {
        size_t row0 = ((size_t)t0 * B_SZ + b) * G3;
        if (active) {
            xr_n = xgd[row0 + j];
            xz_n = xgd[row0 + j + HID];
            xn_n = xgd[row0 + j + 2 * HID];
        }
    }

    for (int s = 0; s < T_LEN; s++) {
        const int t = t0 + s * dt;
        float xr = xr_n, xz = xz_n, xn = xn_n;
        if (s + 1 < T_LEN && active) {
            size_t rown = ((size_t)(t + dt) * B_SZ + b) * G3;
            xr_n = xgd[rown + j];
            xz_n = xgd[rown + j + HID];
            xn_n = xgd[rown + j + 2 * HID];
        }
        float ar = br, az = bz, an = bn;
#pragma unroll
        for (int k = 0; k < HID; k++) {
            float hk = hs[warp][k];
            ar += hk * wr[k];
            az += hk * wz[k];
            an += hk * wn[k];
        }
        if (active) {
            float r = sigf(xr + ar);
            float z = sigf(xz + az);
            float n = tanh_fast(xn + r * an);
            h = (1.0f - z) * n + z * h;
        }
        __syncwarp();
        if (active) hs[warp][j] = h;
        __syncwarp();
        if (active) seq_out[((size_t)t * B_SZ + b) * D2 + d * HID + j] = h;
    }
}

// ---------------- 4) FC epilogue on last timestep ----------------
__global__ void fc_kernel(const float* __restrict__ fc_w, const float* __restrict__ fc_b,
                          const float* __restrict__ omean, const float* __restrict__ ostd,
                          float* __restrict__ out) {
    int idx = blockIdx.x * blockDim.x + threadIdx.x;
    if (idx >= B_SZ * OUTD) return;
    int b = idx / OUTD, o = idx % OUTD;
    const float* last = g_seqA + ((size_t)(T_LEN - 1) * B_SZ + b) * D2;
    float acc = fc_b[o];
#pragma unroll
    for (int k = 0; k < D2; k++) acc += last[k] * fc_w[o * D2 + k];
    out[idx] = acc * ostd[o] + omean[o];
}

// ---------------- launch ----------------
extern "C" void kernel_launch(void* const* d_in, const int* in_sizes, int n_in,
                              void* d_out, int out_size) {
    const float* x         = (const float*)d_in[0];
    const float* fmean     = (const float*)d_in[1];
    const float* fstd      = (const float*)d_in[2];
    const float* omean     = (const float*)d_in[3];
    const float* ostd      = (const float*)d_in[4];
    const float* w_ih_l0   = (const float*)d_in[5];
    const float* w_hh_l0   = (const float*)d_in[6];
    const float* b_ih_l0   = (const float*)d_in[7];
    const float* b_hh_l0   = (const float*)d_in[8];
    const float* w_ih_rest = (const float*)d_in[9];
    const float* w_hh_rest = (const float*)d_in[10];
    const float* b_ih_rest = (const float*)d_in[11];
    const float* b_hh_rest = (const float*)d_in[12];
    const float* fc_w      = (const float*)d_in[13];
    const float* fc_b      = (const float*)d_in[14];
    float* out             = (float*)d_out;

    // 1) normalize + transpose
    {
        size_t total = (size_t)M_ROWS * FIN;
        int threads = 256;
        int blocks = (int)((total + threads - 1) / threads);
        norm_kernel<<<blocks, threads>>>(x, fmean, fstd);
    }

    dim3 xg_grid(M_ROWS / 128, 2);
    dim3 gru_grid(B_SZ / 4, 2);

    // layer 0: xnorm -> seqA
    xg_kernel<FIN><<<xg_grid, 288>>>(0, w_ih_l0, b_ih_l0);
    gru_kernel<<<gru_grid, 128>>>(w_hh_l0, b_hh_l0, /*outsel=*/1);

    // layer 1: seqA -> seqB
    xg_kernel<D2><<<xg_grid, 288>>>(1, w_ih_rest, b_ih_rest);
    gru_kernel<<<gru_grid, 128>>>(w_hh_rest, b_hh_rest, /*outsel=*/2);

    // layer 2: seqB -> seqA
    xg_kernel<D2><<<xg_grid, 288>>>(2, w_ih_rest + (size_t)2 * G3 * D2,
                                    b_ih_rest + 2 * G3);
    gru_kernel<<<gru_grid, 128>>>(w_hh_rest + (size_t)2 * G3 * HID,
                                  b_hh_rest + 2 * G3, /*outsel=*/1);

    // FC epilogue
    {
        int threads = 256;
        int blocks = (B_SZ * OUTD + threads - 1) / threads;
        fc_kernel<<<blocks, threads>>>(fc_w, fc_b, omean, ostd, out);
    }
}

// round 7
// speedup vs baseline: 1.3386x; 1.3386x over previous
#include <cuda_runtime.h>
#include <cstdint>

#define T_LEN 512
#define B_SZ  2048
#define BP    (B_SZ / 2)          // 1024 batch pairs
#define HID   23
#define G3    69                  // 3*H
#define FIN   32
#define D2    46                  // 2*H
#define OUTD  8
#define M_PAIRS ((size_t)T_LEN * BP)   // 524288 row-pairs

// ---------------- scratch (device globals; no allocation) ----------------
// All intermediates are batch-PAIR interleaved: element [..].x = batch 2p, .y = batch 2p+1
__device__ float2 g_xn2[M_PAIRS * FIN];        // [t][bp][32]   134 MB
__device__ float2 g_xg2[2 * M_PAIRS * G3];     // [dir][t*BP+bp][69]  579 MB
__device__ float2 g_sA2[M_PAIRS * D2];         // [t][bp][46]   193 MB
__device__ float2 g_sB2[M_PAIRS * D2];         // [t][bp][46]   193 MB

__device__ __forceinline__ float2 ffma2(float2 a, float2 b, float2 c) {
    union U { float2 f; unsigned long long u; };
    U ua, ub, uc, ud;
    ua.f = a; ub.f = b; uc.f = c;
    asm("fma.rn.f32x2 %0, %1, %2, %3;"
        : "=l"(ud.u) : "l"(ua.u), "l"(ub.u), "l"(uc.u));
    return ud.f;
}

__device__ __forceinline__ float sigf(float x) {
    return 1.0f / (1.0f + __expf(-x));
}
__device__ __forceinline__ float tanh_fast(float x) {
    float a = __expf(-2.0f * fabsf(x));
    float t = (1.0f - a) / (1.0f + a);
    return copysignf(t, x);
}

// ---------------- 1) normalize + transpose [B,T,F] -> pair-interleaved [T,BP,F] ----------------
__global__ void norm_kernel(const float* __restrict__ x,
                            const float* __restrict__ fmean,
                            const float* __restrict__ fstd) {
    size_t idx = (size_t)blockIdx.x * blockDim.x + threadIdx.x;
    size_t total = M_PAIRS * FIN;
    if (idx >= total) return;
    int i = (int)(idx % FIN);
    size_t rp = idx / FIN;
    int bp = (int)(rp % BP);
    int t  = (int)(rp / BP);
    float s = fstd[i];
    s = (s == 0.0f) ? 1.0f : s;
    float2 v;
    if (s == 1.0f) {
        v.x = 0.0f; v.y = 0.0f;
    } else {
        float inv = 1.0f / s;
        float m = fmean[i];
        int b0 = 2 * bp;
        v.x = (x[((size_t)b0 * T_LEN + t) * FIN + i] - m) * inv;
        v.y = (x[((size_t)(b0 + 1) * T_LEN + t) * FIN + i] - m) * inv;
    }
    g_xn2[idx] = v;
}

// ---------------- 2) input-gate GEMM (f32x2): xg2[d][rp][g] = in2[rp] . Wih[d][g] + b ----------
// tile: 128 row-pairs x 72 cols. block = 192 threads; each thread 8 pairs x 6 cols.
template <int K>
__global__ __launch_bounds__(192, 2)
void xg_kernel(int insel, const float* __restrict__ w_ih, const float* __restrict__ b_ih) {
    const float2* in2 = (insel == 0) ? g_xn2 : ((insel == 1) ? g_sA2 : g_sB2);
    const int d = blockIdx.y;
    const float* W = w_ih + (size_t)d * G3 * K;

    extern __shared__ float sdyn[];
    float2* xs2 = (float2*)sdyn;                 // [128][K+1]
    float2* ws2 = xs2 + 128 * (K + 1);           // [72][K+1]  (duplicated splat)
    float*  bs  = (float*)(ws2 + 72 * (K + 1));  // [72]

    const int tid = threadIdx.x;
    const size_t pbase = (size_t)blockIdx.x * 128;

    for (int idx = tid; idx < 128 * K; idx += 192) {
        int p = idx / K, k = idx % K;
        xs2[p * (K + 1) + k] = in2[(pbase + p) * K + k];
    }
    for (int idx = tid; idx < 72 * K; idx += 192) {
        int g = idx / K, k = idx % K;
        float w = (g < G3) ? W[g * K + k] : 0.0f;
        ws2[g * (K + 1) + k] = make_float2(w, w);
    }
    if (tid < 72) bs[tid] = (tid < G3) ? b_ih[d * G3 + tid] : 0.0f;
    __syncthreads();

    const int c0 = (tid % 12) * 6;   // 12 col-groups of 6 -> 72
    const int p0 = (tid / 12) * 8;   // 16 pair-groups of 8 -> 128

    float2 acc[8][6];
#pragma unroll
    for (int i = 0; i < 8; i++)
#pragma unroll
        for (int j = 0; j < 6; j++) { acc[i][j].x = 0.0f; acc[i][j].y = 0.0f; }

#pragma unroll
    for (int k = 0; k < K; k++) {
        float2 wv[6];
#pragma unroll
        for (int j = 0; j < 6; j++) wv[j] = ws2[(c0 + j) * (K + 1) + k];
#pragma unroll
        for (int i = 0; i < 8; i++) {
            float2 xv = xs2[(p0 + i) * (K + 1) + k];
#pragma unroll
            for (int j = 0; j < 6; j++) acc[i][j] = ffma2(xv, wv[j], acc[i][j]);
        }
    }

    float2* xg = g_xg2 + (size_t)d * M_PAIRS * G3;
#pragma unroll
    for (int i = 0; i < 8; i++) {
        size_t rb = (pbase + p0 + i) * (size_t)G3;
#pragma unroll
        for (int j = 0; j < 6; j++) {
            int c = c0 + j;
            if (c < G3) {
                float b = bs[c];
                float2 v = acc[i][j];
                v.x += b; v.y += b;
                xg[rb + c] = v;
            }
        }
    }
}

// ---------------- 3) GRU recurrence (f32x2): one warp per (batch pair, dir) ----------------
__global__ __launch_bounds__(64)
void gru_kernel(const float* __restrict__ w_hh, const float* __restrict__ b_hh, int outsel) {
    const int d = blockIdx.y;
    const int warp = threadIdx.x >> 5;
    const int lane = threadIdx.x & 31;
    const int bp = blockIdx.x * 2 + warp;
    float2* seq2 = (outsel == 1) ? g_sA2 : g_sB2;

    __shared__ float2 hs[2][HID];

    const float* W  = w_hh + (size_t)d * G3 * HID;
    const float* bh = b_hh + d * G3;

    const int j = lane;
    const bool active = (j < HID);
    const int jj = active ? j : 0;   // clamp so inactive lanes load valid addresses

    float2 wr2[HID], wz2[HID], wn2[HID];
#pragma unroll
    for (int k = 0; k < HID; k++) {
        float wr = W[(jj) * HID + k];
        float wz = W[(jj + HID) * HID + k];
        float wn = W[(jj + 2 * HID) * HID + k];
        wr2[k] = make_float2(wr, wr);
        wz2[k] = make_float2(wz, wz);
        wn2[k] = make_float2(wn, wn);
    }
    float brv = bh[jj], bzv = bh[jj + HID], bnv = bh[jj + 2 * HID];
    float2 br2 = make_float2(brv, brv);
    float2 bz2 = make_float2(bzv, bzv);
    float2 bn2 = make_float2(bnv, bnv);

    if (active) hs[warp][j] = make_float2(0.0f, 0.0f);
    float2 h = make_float2(0.0f, 0.0f);
    __syncwarp();

    const float2* xgd = g_xg2 + (size_t)d * M_PAIRS * G3;
    const int t0 = (d == 0) ? 0 : (T_LEN - 1);
    const int dt = (d == 0) ? 1 : -1;

    float2 xr_n, xz_n, xn_n;
    {
        size_t row0 = ((size_t)t0 * BP + bp) * G3;
        xr_n = xgd[row0 + jj];
        xz_n = xgd[row0 + jj + HID];
        xn_n = xgd[row0 + jj + 2 * HID];
    }

    for (int s = 0; s < T_LEN; s++) {
        const int t = t0 + s * dt;
        float2 xr = xr_n, xz = xz_n, xn = xn_n;
        if (s + 1 < T_LEN) {
            size_t rown = ((size_t)(t + dt) * BP + bp) * G3;
            xr_n = xgd[rown + jj];
            xz_n = xgd[rown + jj + HID];
            xn_n = xgd[rown + jj + 2 * HID];
        }
        float2 ar = br2, az = bz2, an = bn2;
#pragma unroll
        for (int k = 0; k < HID; k++) {
            float2 hk = hs[warp][k];
            ar = ffma2(hk, wr2[k], ar);
            az = ffma2(hk, wz2[k], az);
            an = ffma2(hk, wn2[k], an);
        }
        // activations per component (f32x2 has no packed MUFU path)
        float rX = sigf(xr.x + ar.x);
        float rY = sigf(xr.y + ar.y);
        float zX = sigf(xz.x + az.x);
        float zY = sigf(xz.y + az.y);
        float nX = tanh_fast(xn.x + rX * an.x);
        float nY = tanh_fast(xn.y + rY * an.y);
        h.x = (1.0f - zX) * nX + zX * h.x;
        h.y = (1.0f - zY) * nY + zY * h.y;

        __syncwarp();
        if (active) hs[warp][j] = h;
        __syncwarp();
        if (active) seq2[((size_t)t * BP + bp) * D2 + d * HID + j] = h;
    }
}

// ---------------- 4) FC epilogue on last timestep ----------------
__global__ void fc_kernel(const float* __restrict__ fc_w, const float* __restrict__ fc_b,
                          const float* __restrict__ omean, const float* __restrict__ ostd,
                          float* __restrict__ out) {
    int idx = blockIdx.x * blockDim.x + threadIdx.x;
    if (idx >= B_SZ * OUTD) return;
    int b = idx / OUTD, o = idx % OUTD;
    const float* lastp = (const float*)(g_sA2 + ((size_t)(T_LEN - 1) * BP + (b >> 1)) * D2);
    int par = b & 1;
    float acc = fc_b[o];
#pragma unroll
    for (int k = 0; k < D2; k++) acc += lastp[k * 2 + par] * fc_w[o * D2 + k];
    out[idx] = acc * ostd[o] + omean[o];
}

// ---------------- launch ----------------
static inline int xg_smem_bytes(int K) {
    return (128 + 72) * (K + 1) * 8 + 72 * 4;
}

extern "C" void kernel_launch(void* const* d_in, const int* in_sizes, int n_in,
                              void* d_out, int out_size) {
    const float* x         = (const float*)d_in[0];
    const float* fmean     = (const float*)d_in[1];
    const float* fstd      = (const float*)d_in[2];
    const float* omean     = (const float*)d_in[3];
    const float* ostd      = (const float*)d_in[4];
    const float* w_ih_l0   = (const float*)d_in[5];
    const float* w_hh_l0   = (const float*)d_in[6];
    const float* b_ih_l0   = (const float*)d_in[7];
    const float* b_hh_l0   = (const float*)d_in[8];
    const float* w_ih_rest = (const float*)d_in[9];
    const float* w_hh_rest = (const float*)d_in[10];
    const float* b_ih_rest = (const float*)d_in[11];
    const float* b_hh_rest = (const float*)d_in[12];
    const float* fc_w      = (const float*)d_in[13];
    const float* fc_b      = (const float*)d_in[14];
    float* out             = (float*)d_out;

    const int smem32 = xg_smem_bytes(FIN);
    const int smem46 = xg_smem_bytes(D2);
    cudaFuncSetAttribute(xg_kernel<FIN>, cudaFuncAttributeMaxDynamicSharedMemorySize, smem32);
    cudaFuncSetAttribute(xg_kernel<D2>,  cudaFuncAttributeMaxDynamicSharedMemorySize, smem46);

    // 1) normalize + pair transpose
    {
        size_t total = M_PAIRS * FIN;
        int threads = 256;
        int blocks = (int)((total + threads - 1) / threads);
        norm_kernel<<<blocks, threads>>>(x, fmean, fstd);
    }

    dim3 xg_grid((unsigned)(M_PAIRS / 128), 2);
    dim3 gru_grid(BP / 2, 2);

    // layer 0: xn2 -> sA2
    xg_kernel<FIN><<<xg_grid, 192, smem32>>>(0, w_ih_l0, b_ih_l0);
    gru_kernel<<<gru_grid, 64>>>(w_hh_l0, b_hh_l0, /*outsel=*/1);

    // layer 1: sA2 -> sB2
    xg_kernel<D2><<<xg_grid, 192, smem46>>>(1, w_ih_rest, b_ih_rest);
    gru_kernel<<<gru_grid, 64>>>(w_hh_rest, b_hh_rest, /*outsel=*/2);

    // layer 2: sB2 -> sA2
    xg_kernel<D2><<<xg_grid, 192, smem46>>>(2, w_ih_rest + (size_t)2 * G3 * D2,
                                            b_ih_rest + 2 * G3);
    gru_kernel<<<gru_grid, 64>>>(w_hh_rest + (size_t)2 * G3 * HID,
                                 b_hh_rest + 2 * G3, /*outsel=*/1);

    // FC epilogue
    {
        int threads = 256;
        int blocks = (B_SZ * OUTD + threads - 1) / threads;
        fc_kernel<<<blocks, threads>>>(fc_w, fc_b, omean, ostd, out);
    }
}